// round 16
// baseline (speedup 1.0000x reference)
#include <cuda_runtime.h>

// Problem constants (fixed by dataset)
#define LP   640
#define LC   128
#define NODE 128
#define HID  32
#define PAIR 128
#define TILE_I 64   // i-rows per block in pair kernel
#define JPB  2      // j columns per pair block

// Scratch (no allocations allowed -> __device__ globals)
__device__ float g_p[LP * HID];            // LN+Linear of p_embed  [i][c]
__device__ float g_c[LC * HID];            // LN+Linear of c_embed  [j][e]
__device__ float g_Mt[LC * PAIR * HID];    // Mt[j][k][c] = sum_e W3[k,c,e] * c[j,e]

__device__ __forceinline__ float warp_sum(float v) {
#pragma unroll
    for (int o = 16; o; o >>= 1) v += __shfl_xor_sync(0xffffffffu, v, o);
    return v;
}

// packed fp32x2 ops (Blackwell; plain sm_103 PTX, no 'a'-only features)
__device__ __forceinline__ float2 ffma2(float2 a, float2 b, float2 c) {
    float2 d;
    asm("fma.rn.f32x2 %0, %1, %2, %3;"
        : "=l"(reinterpret_cast<unsigned long long&>(d))
        : "l"(reinterpret_cast<const unsigned long long&>(a)),
          "l"(reinterpret_cast<const unsigned long long&>(b)),
          "l"(reinterpret_cast<const unsigned long long&>(c)));
    return d;
}
__device__ __forceinline__ float2 fmul2(float2 a, float2 b) {
    float2 d;
    asm("mul.rn.f32x2 %0, %1, %2;"
        : "=l"(reinterpret_cast<unsigned long long&>(d))
        : "l"(reinterpret_cast<const unsigned long long&>(a)),
          "l"(reinterpret_cast<const unsigned long long&>(b)));
    return d;
}

// ---------------------------------------------------------------------------
// Kernel A: LayerNorm + Linear(NODE->HID). Launched TWICE: first for c rows
// (r0 = LP, grid 128), then for p rows (r0 = 0, grid 640). The c-first split
// lets make_M run as the 2nd launch so pair lands at launch index 4 (the one
// ncu samples). Work is identical to the fused version.
// ---------------------------------------------------------------------------
__global__ void __launch_bounds__(128)
ln_linear_all(const float* __restrict__ p_embed, const float* __restrict__ c_embed,
              const float* __restrict__ ln_p_w, const float* __restrict__ ln_p_b,
              const float* __restrict__ ln_c_w, const float* __restrict__ ln_c_b,
              const float* __restrict__ W_p,   const float* __restrict__ b_p,
              const float* __restrict__ W_c,   const float* __restrict__ b_c,
              int r0)
{
    int r = blockIdx.x + r0;
    bool isp = (r < LP);
    int rr = isp ? r : r - LP;
    const float* emb  = isp ? (p_embed + (size_t)rr * NODE) : (c_embed + (size_t)rr * NODE);
    const float* lnw  = isp ? ln_p_w : ln_c_w;
    const float* lnb  = isp ? ln_p_b : ln_c_b;
    const float* W    = isp ? W_p : W_c;
    const float* bias = isp ? b_p : b_c;
    float* dst        = (isp ? g_p : g_c) + (size_t)rr * HID;

    int t = threadIdx.x;
    __shared__ float part1[4], part2[4];
    __shared__ __align__(16) float s[NODE];

    // one-pass statistics: sum and sumsq reduced with interleaved SHFL chains
    float x  = emb[t];
    float s1 = warp_sum(x);
    float s2 = warp_sum(x * x);
    if ((t & 31) == 0) { part1[t >> 5] = s1; part2[t >> 5] = s2; }
    __syncthreads();
    float mean = (part1[0] + part1[1] + part1[2] + part1[3]) * (1.0f / NODE);
    float ex2  = (part2[0] + part2[1] + part2[2] + part2[3]) * (1.0f / NODE);
    float var  = ex2 - mean * mean;
    float d    = x - mean;
    s[t] = d * rsqrtf(var + 1e-5f) * lnw[t] + lnb[t];
    __syncthreads();

    int w = t >> 5, lane = t & 31;
    float4 sv = ((const float4*)s)[lane];

    float4 wv[8];
#pragma unroll
    for (int rrh = 0; rrh < 8; rrh++)
        wv[rrh] = ((const float4*)(W + (size_t)(w * 8 + rrh) * NODE))[lane];

#pragma unroll
    for (int rrh = 0; rrh < 8; rrh++) {
        int h = w * 8 + rrh;
        float a = wv[rrh].x * sv.x + wv[rrh].y * sv.y
                + wv[rrh].z * sv.z + wv[rrh].w * sv.w;
        a = warp_sum(a);
        if (lane == 0) dst[h] = a + bias[h];
    }
}

// ---------------------------------------------------------------------------
// Kernel B: Mt[j][k][c] = sum_e W_out[k, c*HID + e] * g_c[j, e]
// grid = (LC/8, HID/2), block = 128 (thread = k). W_out staged coalesced,
// padded smem rows -> conflict-free compute reads. float2 stores.
// ---------------------------------------------------------------------------
__global__ void __launch_bounds__(128)
make_M_kernel(const float* __restrict__ Wout)
{
    int k  = threadIdx.x;          // 0..127
    int j0 = blockIdx.x * 8;
    int cb = blockIdx.y;           // c-pair index: global c = cb*2 + {0,1}

    __shared__ float ws[128][67];  // ws[k][c*32+e], padded
    __shared__ float cs[8][HID];

    {
        const float* base = Wout + (size_t)cb * 64;
#pragma unroll
        for (int q = 0; q < 16; q++) {
            int lin4 = q * 128 + k;        // 0..2047 float4s
            int kk   = lin4 >> 4;          // 16 float4 per k
            int x4   = lin4 & 15;
            float4 v = *(const float4*)(base + (size_t)kk * 1024 + x4 * 4);
            ws[kk][x4 * 4 + 0] = v.x;
            ws[kk][x4 * 4 + 1] = v.y;
            ws[kk][x4 * 4 + 2] = v.z;
            ws[kk][x4 * 4 + 3] = v.w;
        }
    }
    for (int idx = k; idx < 8 * HID; idx += 128)
        cs[idx >> 5][idx & 31] = g_c[(size_t)(j0 + (idx >> 5)) * HID + (idx & 31)];
    __syncthreads();

    float acc[8][2];
#pragma unroll
    for (int jj = 0; jj < 8; jj++) { acc[jj][0] = 0.f; acc[jj][1] = 0.f; }

#pragma unroll
    for (int e = 0; e < HID; e++) {
        float w0 = ws[k][e];
        float w1 = ws[k][32 + e];
#pragma unroll
        for (int jj = 0; jj < 8; jj++) {
            float ce = cs[jj][e];
            acc[jj][0] += w0 * ce;
            acc[jj][1] += w1 * ce;
        }
    }
#pragma unroll
    for (int jj = 0; jj < 8; jj++) {
        float2 v = make_float2(acc[jj][0], acc[jj][1]);
        *(float2*)(g_Mt + ((size_t)(j0 + jj) * PAIR + k) * HID + cb * 2) = v;
    }
}

// ---------------------------------------------------------------------------
// Kernel C (main): out[i,j,k] = (sum_c p[i,c]*Mt[j,c,k] + b_out[k]) * mask
// grid = (LP/TILE_I, LC/JPB), block = 256.  BYTE-IDENTICAL to the proven
// 41.4us version -- this round's job is to PROFILE it (4th launch).
// ---------------------------------------------------------------------------
__global__ void __launch_bounds__(256)
pair_kernel(const float* __restrict__ b_out,
            const int* __restrict__ pmask,
            const int* __restrict__ cmask,
            float* __restrict__ out,
            float* __restrict__ outm,   // mask region or nullptr
            int has_mask)
{
    int tid = threadIdx.x;
    int jl  = tid >> 7;                 // 0..1
    int k   = tid & 127;                // 0..127
    int j   = blockIdx.y * JPB + jl;
    int i0  = blockIdx.x * TILE_I;

    // md[c] = (Mt[j][k][c], Mt[j][k][c])
    float2 md[HID];
    {
        const float4* src = (const float4*)(g_Mt + ((size_t)j * PAIR + k) * HID);
#pragma unroll
        for (int q = 0; q < 8; q++) {
            float4 v = src[q];
            md[4*q+0] = make_float2(v.x, v.x);
            md[4*q+1] = make_float2(v.y, v.y);
            md[4*q+2] = make_float2(v.z, v.z);
            md[4*q+3] = make_float2(v.w, v.w);
        }
    }

    __shared__ float  pT[HID][68];          // pT[c][ii], padded rows (272B)
    __shared__ float2 pmc[JPB][TILE_I / 2]; // (pm[i]*cm_j, pm[i+1]*cm_j)

    {
        int c  = tid & 31;
        int ig = tid >> 5;
#pragma unroll
        for (int base = 0; base < TILE_I; base += 8) {
            int ii = base + ig;
            pT[c][ii] = g_p[(size_t)(i0 + ii) * HID + c];
        }
    }
    if (tid < JPB * (TILE_I / 2)) {
        int jl2 = tid / (TILE_I / 2);
        int t   = tid % (TILE_I / 2);
        float cm = cmask[blockIdx.y * JPB + jl2] ? 1.0f : 0.0f;
        float a = pmask[i0 + 2*t]     ? cm : 0.0f;
        float b = pmask[i0 + 2*t + 1] ? cm : 0.0f;
        pmc[jl2][t] = make_float2(a, b);
    }
    // appended inter_mask: 640 blocks x 128 entries = LP*LC
    if (has_mask && jl == 0) {
        int bl  = blockIdx.y * gridDim.x + blockIdx.x;   // 0..639
        int idx = bl * 128 + k;
        int im  = idx >> 7, jm = idx & 127;
        outm[idx] = (pmask[im] && cmask[jm]) ? 1.0f : 0.0f;
    }
    __syncthreads();

    float bk = b_out[k];
    float2 binit = make_float2(bk, bk);
    float* outbase = out + (size_t)i0 * (LC * PAIR) + (size_t)j * PAIR + k;

#pragma unroll 1
    for (int ch = 0; ch < TILE_I / 8; ch++) {
        int li = ch * 8;
        float2 acc0 = binit, acc1 = binit, acc2 = binit, acc3 = binit;
#pragma unroll
        for (int c = 0; c < HID; c++) {
            float4 a = *(const float4*)&pT[c][li];
            float4 b = *(const float4*)&pT[c][li + 4];
            acc0 = ffma2(md[c], make_float2(a.x, a.y), acc0);
            acc1 = ffma2(md[c], make_float2(a.z, a.w), acc1);
            acc2 = ffma2(md[c], make_float2(b.x, b.y), acc2);
            acc3 = ffma2(md[c], make_float2(b.z, b.w), acc3);
        }
        acc0 = fmul2(acc0, pmc[jl][li/2 + 0]);
        acc1 = fmul2(acc1, pmc[jl][li/2 + 1]);
        acc2 = fmul2(acc2, pmc[jl][li/2 + 2]);
        acc3 = fmul2(acc3, pmc[jl][li/2 + 3]);
        outbase[(size_t)(li + 0) * (LC * PAIR)] = acc0.x;
        outbase[(size_t)(li + 1) * (LC * PAIR)] = acc0.y;
        outbase[(size_t)(li + 2) * (LC * PAIR)] = acc1.x;
        outbase[(size_t)(li + 3) * (LC * PAIR)] = acc1.y;
        outbase[(size_t)(li + 4) * (LC * PAIR)] = acc2.x;
        outbase[(size_t)(li + 5) * (LC * PAIR)] = acc2.y;
        outbase[(size_t)(li + 6) * (LC * PAIR)] = acc3.x;
        outbase[(size_t)(li + 7) * (LC * PAIR)] = acc3.y;
    }
}

extern "C" void kernel_launch(void* const* d_in, const int* in_sizes, int n_in,
                              void* d_out, int out_size)
{
    const float* p_embed = (const float*)d_in[0];
    const float* c_embed = (const float*)d_in[1];
    const int*   p_mask  = (const int*)d_in[2];
    const int*   c_mask  = (const int*)d_in[3];
    const float* ln_p_w  = (const float*)d_in[4];
    const float* ln_p_b  = (const float*)d_in[5];
    const float* ln_c_w  = (const float*)d_in[6];
    const float* ln_c_b  = (const float*)d_in[7];
    const float* W_p     = (const float*)d_in[8];
    const float* b_p     = (const float*)d_in[9];
    const float* W_c     = (const float*)d_in[10];
    const float* b_c     = (const float*)d_in[11];
    const float* W_out   = (const float*)d_in[12];
    const float* b_out   = (const float*)d_in[13];
    float* out = (float*)d_out;

    // Launch order chosen so pair_kernel is the 4th launch (ncu sample slot):
    // 1) LN+Linear for c rows only  2) make_M  3) LN+Linear for p rows  4) pair
    ln_linear_all<<<LC, 128>>>(p_embed, c_embed, ln_p_w, ln_p_b,
                               ln_c_w, ln_c_b, W_p, b_p, W_c, b_c, LP);

    dim3 gB(LC / 8, HID / 2);
    make_M_kernel<<<gB, 128>>>(W_out);

    ln_linear_all<<<LP, 128>>>(p_embed, c_embed, ln_p_w, ln_p_b,
                               ln_c_w, ln_c_b, W_p, b_p, W_c, b_c, 0);

    long long main_elems = (long long)LP * LC * PAIR;
    int has_mask = ((long long)out_size >= main_elems + (long long)LP * LC) ? 1 : 0;
    float* outm = out + main_elems;

    dim3 gC(LP / TILE_I, LC / JPB);
    pair_kernel<<<gC, 256>>>(b_out, p_mask, c_mask, out, outm, has_mask);
}

// round 17
// speedup vs baseline: 1.0066x; 1.0066x over previous
#include <cuda_runtime.h>

// Problem constants (fixed by dataset)
#define LP   640
#define LC   128
#define NODE 128
#define HID  32
#define PAIR 128
#define TILE_I 64   // i-rows per block in pair kernel
#define JPB  2      // j columns per pair block

// Scratch (no allocations allowed -> __device__ globals)
__device__ float g_p[LP * HID];            // LN+Linear of p_embed  [i][c]
__device__ float g_c[LC * HID];            // LN+Linear of c_embed  [j][e]
__device__ float g_Mt[LC * HID * PAIR];    // Mt[j][c][k] (k contiguous)

__device__ __forceinline__ float warp_sum(float v) {
#pragma unroll
    for (int o = 16; o; o >>= 1) v += __shfl_xor_sync(0xffffffffu, v, o);
    return v;
}

// packed fp32x2 ops (plain sm_103 PTX)
__device__ __forceinline__ float2 ffma2(float2 a, float2 b, float2 c) {
    float2 d;
    asm("fma.rn.f32x2 %0, %1, %2, %3;"
        : "=l"(reinterpret_cast<unsigned long long&>(d))
        : "l"(reinterpret_cast<const unsigned long long&>(a)),
          "l"(reinterpret_cast<const unsigned long long&>(b)),
          "l"(reinterpret_cast<const unsigned long long&>(c)));
    return d;
}
__device__ __forceinline__ float2 fmul2(float2 a, float2 b) {
    float2 d;
    asm("mul.rn.f32x2 %0, %1, %2;"
        : "=l"(reinterpret_cast<unsigned long long&>(d))
        : "l"(reinterpret_cast<const unsigned long long&>(a)),
          "l"(reinterpret_cast<const unsigned long long&>(b)));
    return d;
}

// ---------------------------------------------------------------------------
// Kernel A: LayerNorm + Linear(NODE->HID). Launched twice (c rows first,
// then p rows) so pair lands in the ncu sample slot (4th launch).
// ---------------------------------------------------------------------------
__global__ void __launch_bounds__(128)
ln_linear_all(const float* __restrict__ p_embed, const float* __restrict__ c_embed,
              const float* __restrict__ ln_p_w, const float* __restrict__ ln_p_b,
              const float* __restrict__ ln_c_w, const float* __restrict__ ln_c_b,
              const float* __restrict__ W_p,   const float* __restrict__ b_p,
              const float* __restrict__ W_c,   const float* __restrict__ b_c,
              int r0)
{
    int r = blockIdx.x + r0;
    bool isp = (r < LP);
    int rr = isp ? r : r - LP;
    const float* emb  = isp ? (p_embed + (size_t)rr * NODE) : (c_embed + (size_t)rr * NODE);
    const float* lnw  = isp ? ln_p_w : ln_c_w;
    const float* lnb  = isp ? ln_p_b : ln_c_b;
    const float* W    = isp ? W_p : W_c;
    const float* bias = isp ? b_p : b_c;
    float* dst        = (isp ? g_p : g_c) + (size_t)rr * HID;

    int t = threadIdx.x;
    __shared__ float part1[4], part2[4];
    __shared__ __align__(16) float s[NODE];

    float x  = emb[t];
    float s1 = warp_sum(x);
    float s2 = warp_sum(x * x);
    if ((t & 31) == 0) { part1[t >> 5] = s1; part2[t >> 5] = s2; }
    __syncthreads();
    float mean = (part1[0] + part1[1] + part1[2] + part1[3]) * (1.0f / NODE);
    float ex2  = (part2[0] + part2[1] + part2[2] + part2[3]) * (1.0f / NODE);
    float var  = ex2 - mean * mean;
    float d    = x - mean;
    s[t] = d * rsqrtf(var + 1e-5f) * lnw[t] + lnb[t];
    __syncthreads();

    int w = t >> 5, lane = t & 31;
    float4 sv = ((const float4*)s)[lane];

    float4 wv[8];
#pragma unroll
    for (int rrh = 0; rrh < 8; rrh++)
        wv[rrh] = ((const float4*)(W + (size_t)(w * 8 + rrh) * NODE))[lane];

#pragma unroll
    for (int rrh = 0; rrh < 8; rrh++) {
        int h = w * 8 + rrh;
        float a = wv[rrh].x * sv.x + wv[rrh].y * sv.y
                + wv[rrh].z * sv.z + wv[rrh].w * sv.w;
        a = warp_sum(a);
        if (lane == 0) dst[h] = a + bias[h];
    }
}

// ---------------------------------------------------------------------------
// Kernel B: Mt[j][c][k] = sum_e W_out[k, c*HID + e] * g_c[j, e]
// grid = (LC/8, HID/2), block = 128 (thread = k). Stores scalar, coalesced
// over k, into the [j][c][k] layout the pair kernel consumes.
// ---------------------------------------------------------------------------
__global__ void __launch_bounds__(128)
make_M_kernel(const float* __restrict__ Wout)
{
    int k  = threadIdx.x;          // 0..127
    int j0 = blockIdx.x * 8;
    int cb = blockIdx.y;           // c-pair index: global c = cb*2 + {0,1}

    __shared__ float ws[128][67];  // ws[k][c*32+e], padded
    __shared__ float cs[8][HID];

    {
        const float* base = Wout + (size_t)cb * 64;
#pragma unroll
        for (int q = 0; q < 16; q++) {
            int lin4 = q * 128 + k;        // 0..2047 float4s
            int kk   = lin4 >> 4;          // 16 float4 per k
            int x4   = lin4 & 15;
            float4 v = *(const float4*)(base + (size_t)kk * 1024 + x4 * 4);
            ws[kk][x4 * 4 + 0] = v.x;
            ws[kk][x4 * 4 + 1] = v.y;
            ws[kk][x4 * 4 + 2] = v.z;
            ws[kk][x4 * 4 + 3] = v.w;
        }
    }
    for (int idx = k; idx < 8 * HID; idx += 128)
        cs[idx >> 5][idx & 31] = g_c[(size_t)(j0 + (idx >> 5)) * HID + (idx & 31)];
    __syncthreads();

    float acc[8][2];
#pragma unroll
    for (int jj = 0; jj < 8; jj++) { acc[jj][0] = 0.f; acc[jj][1] = 0.f; }

#pragma unroll
    for (int e = 0; e < HID; e++) {
        float w0 = ws[k][e];
        float w1 = ws[k][32 + e];
#pragma unroll
        for (int jj = 0; jj < 8; jj++) {
            float ce = cs[jj][e];
            acc[jj][0] += w0 * ce;
            acc[jj][1] += w1 * ce;
        }
    }
#pragma unroll
    for (int jj = 0; jj < 8; jj++) {
        g_Mt[((size_t)(j0 + jj) * HID + cb * 2 + 0) * PAIR + k] = acc[jj][0];
        g_Mt[((size_t)(j0 + jj) * HID + cb * 2 + 1) * PAIR + k] = acc[jj][1];
    }
}

// ---------------------------------------------------------------------------
// Kernel C (main): out[i,j,k] = (sum_c p[i,c]*Mt[j,c,k] + b_out[k]) * mask
// grid = (LP/64, LC/2), block = 256. Register-tiled: each thread owns an
// 8i x 8k output tile (acc = 32 float2). Per c: 2 m-LDS.128 (k quad-
// interleaved, 2-phase) + 4 p-LDS.128 (duplicated, broadcast) + 32 FFMA2.
// Static smem exactly 48KB: sm_m 32KB + pd 16KB.
// ---------------------------------------------------------------------------
__global__ void __launch_bounds__(256, 2)
pair_kernel(const float* __restrict__ b_out,
            const int* __restrict__ pmask,
            const int* __restrict__ cmask,
            float* __restrict__ out,
            float* __restrict__ outm,   // mask region or nullptr
            int has_mask)
{
    __shared__ float  sm_m[JPB][HID][PAIR];   // [j][c][k-interleaved]  32KB
    __shared__ __align__(16) float2 pd[HID][TILE_I]; // duplicated p    16KB

    int tid = threadIdx.x;
    int tx  = tid & 15;                 // k-group: k0 = tx*8
    int ty  = (tid >> 4) & 7;           // i-group: i_loc = ty*8 + ih
    int jl  = tid >> 7;                 // 0..1
    int j   = blockIdx.y * JPB + jl;
    int i0  = blockIdx.x * TILE_I;
    int k0  = tx * 8;

    // Fill sm_m: coalesced read of both j tiles, quad-interleaved scatter.
    {
        const float* src = g_Mt + (size_t)(blockIdx.y * JPB) * (HID * PAIR);
#pragma unroll
        for (int q = 0; q < 32; q++) {
            int lin = q * 256 + tid;            // 0..8191
            int jj  = lin >> 12;
            int c   = (lin >> 7) & 31;
            int k   = lin & 127;
            int si  = ((k >> 2) & 1) * 64 + (k >> 3) * 4 + (k & 3);
            sm_m[jj][c][si] = src[lin];
        }
    }
    // Fill pd: coalesced read of p tile, duplicated write.
    {
        int c   = tid & 31;
        int ii0 = tid >> 5;                     // 0..7
#pragma unroll
        for (int rep = 0; rep < 8; rep++) {
            int ii = ii0 + rep * 8;
            float v = g_p[(size_t)(i0 + ii) * HID + c];
            pd[c][ii] = make_float2(v, v);
        }
    }
    // appended inter_mask: 640 blocks x 128 entries = LP*LC
    if (has_mask && tid < 128) {
        int bl  = blockIdx.y * gridDim.x + blockIdx.x;   // 0..639
        int idx = bl * 128 + tid;
        outm[idx] = (pmask[idx >> 7] && cmask[idx & 127]) ? 1.0f : 0.0f;
    }
    __syncthreads();

    // acc init from bias
    float4 bA = *(const float4*)(b_out + k0);
    float4 bB = *(const float4*)(b_out + k0 + 4);
    float2 b01 = make_float2(bA.x, bA.y), b23 = make_float2(bA.z, bA.w);
    float2 b45 = make_float2(bB.x, bB.y), b67 = make_float2(bB.z, bB.w);

    float2 acc[8][4];
#pragma unroll
    for (int ih = 0; ih < 8; ih++) {
        acc[ih][0] = b01; acc[ih][1] = b23; acc[ih][2] = b45; acc[ih][3] = b67;
    }

    const float4* mrow_base = (const float4*)&sm_m[jl][0][0];
    const float4* prow_base = (const float4*)&pd[0][0];

#pragma unroll 8
    for (int c = 0; c < HID; c++) {
        const float4* mrow = mrow_base + c * 32;        // 128 floats / 4
        float4 m0 = mrow[tx];        // k0..k3 pairs
        float4 m1 = mrow[16 + tx];   // k4..k7 pairs
        float2 mk01 = make_float2(m0.x, m0.y), mk23 = make_float2(m0.z, m0.w);
        float2 mk45 = make_float2(m1.x, m1.y), mk67 = make_float2(m1.z, m1.w);
        const float4* prow = prow_base + c * 32;        // 64 float2 / 2
#pragma unroll
        for (int ph = 0; ph < 4; ph++) {
            float4 pp = prow[ty * 4 + ph];              // 2 duplicated p's
            float2 d0 = make_float2(pp.x, pp.y);
            float2 d1 = make_float2(pp.z, pp.w);
            acc[2*ph+0][0] = ffma2(mk01, d0, acc[2*ph+0][0]);
            acc[2*ph+0][1] = ffma2(mk23, d0, acc[2*ph+0][1]);
            acc[2*ph+0][2] = ffma2(mk45, d0, acc[2*ph+0][2]);
            acc[2*ph+0][3] = ffma2(mk67, d0, acc[2*ph+0][3]);
            acc[2*ph+1][0] = ffma2(mk01, d1, acc[2*ph+1][0]);
            acc[2*ph+1][1] = ffma2(mk23, d1, acc[2*ph+1][1]);
            acc[2*ph+1][2] = ffma2(mk45, d1, acc[2*ph+1][2]);
            acc[2*ph+1][3] = ffma2(mk67, d1, acc[2*ph+1][3]);
        }
    }

    // Epilogue: mask and store (2 STG.128 per i-row)
    float cm = cmask[j] ? 1.0f : 0.0f;
#pragma unroll
    for (int ih = 0; ih < 8; ih++) {
        int i = i0 + ty * 8 + ih;
        float s = pmask[i] ? cm : 0.0f;
        float2 sd = make_float2(s, s);
        float2 a0 = fmul2(acc[ih][0], sd);
        float2 a1 = fmul2(acc[ih][1], sd);
        float2 a2 = fmul2(acc[ih][2], sd);
        float2 a3 = fmul2(acc[ih][3], sd);
        float* ob = out + (size_t)i * (LC * PAIR) + (size_t)j * PAIR + k0;
        *(float4*)(ob)     = make_float4(a0.x, a0.y, a1.x, a1.y);
        *(float4*)(ob + 4) = make_float4(a2.x, a2.y, a3.x, a3.y);
    }
}

extern "C" void kernel_launch(void* const* d_in, const int* in_sizes, int n_in,
                              void* d_out, int out_size)
{
    const float* p_embed = (const float*)d_in[0];
    const float* c_embed = (const float*)d_in[1];
    const int*   p_mask  = (const int*)d_in[2];
    const int*   c_mask  = (const int*)d_in[3];
    const float* ln_p_w  = (const float*)d_in[4];
    const float* ln_p_b  = (const float*)d_in[5];
    const float* ln_c_w  = (const float*)d_in[6];
    const float* ln_c_b  = (const float*)d_in[7];
    const float* W_p     = (const float*)d_in[8];
    const float* b_p     = (const float*)d_in[9];
    const float* W_c     = (const float*)d_in[10];
    const float* b_c     = (const float*)d_in[11];
    const float* W_out   = (const float*)d_in[12];
    const float* b_out   = (const float*)d_in[13];
    float* out = (float*)d_out;

    // 4-launch order keeps pair in the ncu sample slot:
    // 1) LN+Linear c rows  2) make_M  3) LN+Linear p rows  4) pair
    ln_linear_all<<<LC, 128>>>(p_embed, c_embed, ln_p_w, ln_p_b,
                               ln_c_w, ln_c_b, W_p, b_p, W_c, b_c, LP);

    dim3 gB(LC / 8, HID / 2);
    make_M_kernel<<<gB, 128>>>(W_out);

    ln_linear_all<<<LP, 128>>>(p_embed, c_embed, ln_p_w, ln_p_b,
                               ln_c_w, ln_c_b, W_p, b_p, W_c, b_c, 0);

    long long main_elems = (long long)LP * LC * PAIR;
    int has_mask = ((long long)out_size >= main_elems + (long long)LP * LC) ? 1 : 0;
    float* outm = out + main_elems;

    dim3 gC(LP / TILE_I, LC / JPB);
    pair_kernel<<<gC, 256>>>(b_out, p_mask, c_mask, out, outm, has_mask);
}